// round 8
// baseline (speedup 1.0000x reference)
#include <cuda_runtime.h>
#include <math.h>

#define D_     1024
#define BLK    256
#define GRID1  592        // pass1: 4 CTA/SM * 148
#define GRID2  740        // pass2: 5 CTA/SM * 148
#define ROWS_  8
#define PAIRS  4
#define NMAX   512
#define MMAX   16384
#define EPS_   1e-5f

typedef unsigned long long ull;
union F4U { float4 f4; ulonglong2 u2; };

// ---- scratch (static device globals; no allocation) ----
__device__ float g_colpart[GRID1 * D_];
__device__ float g_gate[MMAX];
__device__ float g_mean[D_];
__device__ float g_sims[NMAX];
__device__ int   g_valid[NMAX];
__device__ float g_damp, g_qscale;
__device__ int   g_nidx;
__device__ int   g_ctr = 0;
__device__ int   g_ctr2 = 0;

// ---- packed f32x2 helpers ----
__device__ __forceinline__ ull pk2(float lo, float hi) {
    ull r; asm("mov.b64 %0, {%1, %2};" : "=l"(r) : "f"(lo), "f"(hi)); return r;
}
__device__ __forceinline__ float2 upk2(ull v) {
    float2 f; asm("mov.b64 {%0, %1}, %2;" : "=f"(f.x), "=f"(f.y) : "l"(v)); return f;
}
__device__ __forceinline__ ull fma2p(ull a, ull b, ull c) {
    ull r; asm("fma.rn.f32x2 %0, %1, %2, %3;" : "=l"(r) : "l"(a), "l"(b), "l"(c)); return r;
}
__device__ __forceinline__ ull mul2p(ull a, ull b) {
    ull r; asm("mul.rn.f32x2 %0, %1, %2;" : "=l"(r) : "l"(a), "l"(b)); return r;
}

__device__ __forceinline__ float wsum(float v) {
    v += __shfl_xor_sync(0xffffffffu, v, 16);
    v += __shfl_xor_sync(0xffffffffu, v, 8);
    v += __shfl_xor_sync(0xffffffffu, v, 4);
    v += __shfl_xor_sync(0xffffffffu, v, 2);
    v += __shfl_xor_sync(0xffffffffu, v, 1);
    return v;
}
__device__ __forceinline__ float bfly(float a, float b, int lane, int m) {
    float sent = (lane & m) ? a : b;
    float recv = __shfl_xor_sync(0xffffffffu, sent, m);
    return ((lane & m) ? b : a) + recv;
}
__device__ __forceinline__ float tanh_ap(float u) {
    float r; asm("tanh.approx.f32 %0, %1;" : "=f"(r) : "f"(u)); return r;
}

// packed gelu: y = 0.5x(1+tanh(C(x + a x^3))) for an f32 pair
__device__ __forceinline__ ull gelu2p(ull x2) {
    const ull A2   = pk2(0.044715f, 0.044715f);
    const ull ONE2 = pk2(1.0f, 1.0f);
    const ull C2   = pk2(0.7978845608028654f, 0.7978845608028654f);
    const ull H2   = pk2(0.5f, 0.5f);
    ull t2 = mul2p(x2, x2);
    ull p2 = fma2p(t2, A2, ONE2);
    ull u2 = mul2p(mul2p(x2, C2), p2);
    float2 u = upk2(u2);
    ull T2 = pk2(tanh_ap(u.x), tanh_ap(u.y));
    ull hx2 = mul2p(x2, H2);
    return fma2p(T2, hx2, hx2);
}
// packed gelu with folded scale gs: y = gs*x*(1+tanh(u))
__device__ __forceinline__ ull gelu2s(ull x2, ull gs2) {
    const ull A2   = pk2(0.044715f, 0.044715f);
    const ull ONE2 = pk2(1.0f, 1.0f);
    const ull C2   = pk2(0.7978845608028654f, 0.7978845608028654f);
    ull t2 = mul2p(x2, x2);
    ull p2 = fma2p(t2, A2, ONE2);
    ull u2 = mul2p(mul2p(x2, C2), p2);
    float2 u = upk2(u2);
    ull T2 = pk2(tanh_ap(u.x), tanh_ap(u.y));
    ull hx2 = mul2p(x2, gs2);
    return fma2p(T2, hx2, hx2);
}

// ---------------- pass 1: gates + y1 column partial sums ----------------
__global__ void __launch_bounds__(BLK, 4) k_pass1(
    const float* __restrict__ x,
    const float* __restrict__ ema_x, const float* __restrict__ ema_x2,
    const float* __restrict__ ema_y, const float* __restrict__ ema_y2,
    const float* __restrict__ p_lt_in, const float* __restrict__ p_lt_out,
    const float* __restrict__ p_la_in, const float* __restrict__ p_la_out,
    int M)
{
    const int t = threadIdx.x;
    const int c = t * 4;
    const int lane = t & 31, w = t >> 5;

    float4 ex = *(const float4*)(ema_x + c);
    float4 e2 = *(const float4*)(ema_x2 + c);
    float4 ey = *(const float4*)(ema_y + c);
    float4 f2 = *(const float4*)(ema_y2 + c);
    float i0 = 1.0f / (sqrtf(fmaxf(e2.x - ex.x * ex.x, 0.0f)) + EPS_);
    float i1 = 1.0f / (sqrtf(fmaxf(e2.y - ex.y * ex.y, 0.0f)) + EPS_);
    float i2 = 1.0f / (sqrtf(fmaxf(e2.z - ex.z * ex.z, 0.0f)) + EPS_);
    float i3 = 1.0f / (sqrtf(fmaxf(e2.w - ex.w * ex.w, 0.0f)) + EPS_);
    float j0 = 1.0f / (sqrtf(fmaxf(f2.x - ey.x * ey.x, 0.0f)) + EPS_);
    float j1 = 1.0f / (sqrtf(fmaxf(f2.y - ey.y * ey.y, 0.0f)) + EPS_);
    float j2 = 1.0f / (sqrtf(fmaxf(f2.z - ey.z * ey.z, 0.0f)) + EPS_);
    float j3 = 1.0f / (sqrtf(fmaxf(f2.w - ey.w * ey.w, 0.0f)) + EPS_);
    const ull ISX0 = pk2(i0, i1), ISX1 = pk2(i2, i3);
    const ull NX0  = pk2(-ex.x * i0, -ex.y * i1), NX1 = pk2(-ex.z * i2, -ex.w * i3);
    const ull ISY0 = pk2(j0, j1), ISY1 = pk2(j2, j3);
    const ull NY0  = pk2(-ey.x * j0, -ey.y * j1), NY1 = pk2(-ey.z * j2, -ey.w * j3);

    const float tau_in  = expf(p_lt_in[0]);
    const float tau_out = expf(p_lt_out[0]);
    const float a_in    = 1.0f / (1.0f + expf(-p_la_in[0]));
    const float a_out   = 1.0f / (1.0f + expf(-p_la_out[0]));
    const int li = lane & 15;
    const bool isin = (li < 8);
    const float tau_l = isin ? tau_in : tau_out;
    const float a_l   = isin ? a_in : a_out;
    const float b_l   = 1.0f - a_l;

    __shared__ float s_red[2][8][16];

    ull acc0 = 0ull, acc1 = 0ull;   // packed zeros (0.0f,0.0f)
    const int nchunk = M / ROWS_;
    int parity = 0;

    for (int ch = blockIdx.x; ch < nchunk; ch += GRID1, parity ^= 1) {
        const float* xp = x + (size_t)ch * (ROWS_ * D_) + c;
        ull xa[ROWS_], xb[ROWS_];
#pragma unroll
        for (int r = 0; r < ROWS_; r++) {
            F4U X; X.f4 = *(const float4*)(xp + r * D_);
            xa[r] = X.u2.x; xb[r] = X.u2.y;
        }

        ull ya[ROWS_], yb[ROWS_];
        float zx[ROWS_], zy[ROWS_];
#pragma unroll
        for (int r = 0; r < ROWS_; r++) {
            ya[r] = gelu2p(xa[r]);
            yb[r] = gelu2p(xb[r]);
            ull da = fma2p(xa[r], ISX0, NX0);
            ull db = fma2p(xb[r], ISX1, NX1);
            ull sx = fma2p(db, db, mul2p(da, da));
            float2 fx = upk2(sx); zx[r] = fx.x + fx.y;
            ull ga_ = fma2p(ya[r], ISY0, NY0);
            ull gb_ = fma2p(yb[r], ISY1, NY1);
            ull sy = fma2p(gb_, gb_, mul2p(ga_, ga_));
            float2 fy = upk2(sy); zy[r] = fy.x + fy.y;
        }

        // 16-value butterfly reduce
        float v[8];
#pragma unroll
        for (int r = 0; r < 8; r++) v[r] = bfly(zx[r], zy[r], lane, 16);
        float u0 = bfly(v[0], v[4], lane, 8);
        float u1 = bfly(v[1], v[5], lane, 8);
        float u2 = bfly(v[2], v[6], lane, 8);
        float u3 = bfly(v[3], v[7], lane, 8);
        float s0 = bfly(u0, u2, lane, 4);
        float s1 = bfly(u1, u3, lane, 4);
        float z  = bfly(s0, s1, lane, 2);
        z += __shfl_xor_sync(0xffffffffu, z, 1);

        if ((lane & 1) == 0) {
            int idx = ((lane & 14) >> 1) | ((lane & 16) >> 1);
            s_red[parity][w][idx] = z;
        }
        __syncthreads();

        float zsum = 0.f;
#pragma unroll
        for (int ww = 0; ww < 8; ww++) zsum += s_red[parity][ww][li];
        zsum *= (1.0f / D_);
        float f = fmaf(a_l, __expf(-tau_l * zsum), b_l);
        float fo = __shfl_sync(0xffffffffu, f, (lane & 7) + 8);
        float g = f * fo;
        if (w == 0 && lane < 8) g_gate[ch * ROWS_ + lane] = g;
#pragma unroll
        for (int r = 0; r < ROWS_; r++) {
            float ga = __shfl_sync(0xffffffffu, g, r);
            ull GA2 = pk2(ga, ga);
            acc0 = fma2p(ya[r], GA2, acc0);
            acc1 = fma2p(yb[r], GA2, acc1);
        }
    }
    F4U A; A.u2.x = acc0; A.u2.y = acc1;
    *(float4*)(g_colpart + blockIdx.x * D_ + c) = A.f4;
}

// ------------- fused colreduce + sims + select (512 x 128) --------------
__global__ void __launch_bounds__(128) k_mid(
    const float* __restrict__ buf, const float* __restrict__ facil,
    const float* __restrict__ p_lkb, const float* __restrict__ p_lkd,
    int N, float invM)
{
    const int n = blockIdx.x;
    const int t = threadIdx.x;
    const int lane = t & 31, w = t >> 5;

    if (n < 128) {
        const int col = n * 8 + (t & 7);
        const int gs = t >> 3;                 // 0..15
        float s = 0.f;
#pragma unroll
        for (int k = 0; k < GRID1 / 16; k++)   // 37 slices
            s += g_colpart[(gs + k * 16) * D_ + col];
        __shared__ float sm[16][8];
        sm[gs][t & 7] = s;
        __syncthreads();
        if (t < 8) {
            float tot = 0.f;
#pragma unroll
            for (int i = 0; i < 16; i++) tot += sm[i][t];
            g_mean[n * 8 + t] = tot * invM;
        }
        if (t == 0) { __threadfence(); atomicAdd(&g_ctr2, 1); }
    }
    if (t == 0) {
        while (atomicAdd(&g_ctr2, 0) < 128) { }
    }
    __syncthreads();

    const float4* bp = (const float4*)(buf + (size_t)n * D_);
    const float4* mp = (const float4*)g_mean;
    float dot = 0.f, b2 = 0.f, m2 = 0.f;
    int fin = 1;
#pragma unroll
    for (int k = 0; k < 2; k++) {
        float4 bv = bp[t + k * 128];
        float4 mv = mp[t + k * 128];
        dot = fmaf(bv.x, mv.x, fmaf(bv.y, mv.y, fmaf(bv.z, mv.z, fmaf(bv.w, mv.w, dot))));
        b2  = fmaf(bv.x, bv.x, fmaf(bv.y, bv.y, fmaf(bv.z, bv.z, fmaf(bv.w, bv.w, b2))));
        m2  = fmaf(mv.x, mv.x, fmaf(mv.y, mv.y, fmaf(mv.z, mv.z, fmaf(mv.w, mv.w, m2))));
        fin &= (fabsf(bv.x) <= 3.4028234e38f) & (fabsf(bv.y) <= 3.4028234e38f) &
               (fabsf(bv.z) <= 3.4028234e38f) & (fabsf(bv.w) <= 3.4028234e38f);
    }
    dot = wsum(dot); b2 = wsum(b2); m2 = wsum(m2);
    fin = __all_sync(0xffffffffu, fin);
    __shared__ float sd[4], sb[4], sm2[4];
    __shared__ int sf[4];
    if (lane == 0) { sd[w] = dot; sb[w] = b2; sm2[w] = m2; sf[w] = fin; }
    __syncthreads();
    if (t == 0) {
        float dt = sd[0] + sd[1] + sd[2] + sd[3];
        float bb = sb[0] + sb[1] + sb[2] + sb[3];
        float mm = sm2[0] + sm2[1] + sm2[2] + sm2[3];
        float bnorm = fmaxf(sqrtf(bb), 1e-12f);
        float mnorm = fmaxf(sqrtf(mm), 1e-12f);
        g_sims[n] = dt / (bnorm * mnorm);
        g_valid[n] = (sf[0] & sf[1] & sf[2] & sf[3]) && (sqrtf(bb) >= 1e-6f);
    }
    __shared__ int is_last;
    if (t == 0) {
        __threadfence();
        int c = atomicAdd(&g_ctr, 1);
        is_last = (c == gridDim.x - 1) ? 1 : 0;
    }
    __syncthreads();
    if (!is_last) return;

    float best = -3.0e38f; int bidx = 0x7fffffff;
    for (int i = t; i < N; i += 128) {
        float v = g_sims[i];
        if (v > best) { best = v; bidx = i; }
    }
#pragma unroll
    for (int o = 16; o > 0; o >>= 1) {
        float ov = __shfl_xor_sync(0xffffffffu, best, o);
        int   oi = __shfl_xor_sync(0xffffffffu, bidx, o);
        if (ov > best || (ov == best && oi < bidx)) { best = ov; bidx = oi; }
    }
    __shared__ float svv[4]; __shared__ int sii[4];
    if (lane == 0) { svv[w] = best; sii[w] = bidx; }
    __syncthreads();
    if (t == 0) {
        float bv = svv[0]; int bi = sii[0];
#pragma unroll
        for (int i = 1; i < 4; i++) {
            if (svv[i] > bv || (svv[i] == bv && sii[i] < bi)) { bv = svv[i]; bi = sii[i]; }
        }
        float sim_val = fminf(fmaxf(bv, 0.0f), 1.0f);
        float kb = fminf(fmaxf(expf(p_lkb[0]), 0.01f), 4.0f);
        float kd = fminf(fmaxf(expf(p_lkd[0]), 0.01f), 0.9f);
        float fl = facil[bi] * ((sim_val > 0.88f) ? 2.0f : 1.0f);
        float mod = (fl - 1.0f) * sim_val;
        float boost = 1.0f + kb * mod;
        float damp = fmaxf(0.01f, 1.0f - kd * mod);
        g_nidx = bi;
        if (g_valid[bi]) { g_damp = damp; g_qscale = (boost - damp) / damp; }
        else             { g_damp = 1.0f; g_qscale = 0.0f; }
        g_ctr = 0;
        g_ctr2 = 0;
    }
}

// ---------------- pass 2: warp-pair per row, packed f32x2 ---------------
__global__ void __launch_bounds__(BLK, 5) k_pass2(
    const float* __restrict__ x, const float* __restrict__ buf,
    float* __restrict__ out, int M)
{
    __shared__ float4 s_v[D_ / 4];
    __shared__ float s_p[2][PAIRS][2];
    const int t = threadIdx.x;
    const int lane = t & 31, w = t >> 5;
    const int pair = w >> 1, half = w & 1;
    const float damp = g_damp;
    const float qscale = g_qscale;
    const int ni = g_nidx;

    {
        const float4* vp = (const float4*)(buf + (size_t)ni * D_);
        for (int i = t; i < D_ / 4; i += BLK) s_v[i] = vp[i];
    }
    __syncthreads();

    const int voff = half * 128 + lane;
    int parity = 0;
    for (int row = blockIdx.x * PAIRS + pair; row < M;
         row += GRID2 * PAIRS, parity ^= 1) {
        const float4* xp = (const float4*)(x + (size_t)row * D_) + voff;
        const float gad = 0.5f * damp * g_gate[row];
        const ull GAD2 = pk2(gad, gad);
        ull Ya[4], Yb[4];
        ull pj2 = 0ull;
#pragma unroll
        for (int k = 0; k < 4; k++) {
            F4U X; X.f4 = __ldcs(xp + 32 * k);
            F4U V; V.f4 = s_v[voff + 32 * k];
            ull ya = gelu2s(X.u2.x, GAD2);
            ull yb = gelu2s(X.u2.y, GAD2);
            Ya[k] = ya; Yb[k] = yb;
            pj2 = fma2p(ya, V.u2.x, pj2);
            pj2 = fma2p(yb, V.u2.y, pj2);
        }
        float2 pj = upk2(pj2);
        float proj = wsum(pj.x + pj.y);
        if (lane == 0) s_p[parity][pair][half] = proj;
        asm volatile("bar.sync %0, %1;" :: "r"(pair + 1), "r"(64) : "memory");
        const float q = (s_p[parity][pair][0] + s_p[parity][pair][1]) * qscale;
        const ull Q2 = pk2(q, q);
        float4* op = (float4*)(out + (size_t)row * D_) + voff;
#pragma unroll
        for (int k = 0; k < 4; k++) {
            F4U V; V.f4 = s_v[voff + 32 * k];
            F4U O;
            O.u2.x = fma2p(Q2, V.u2.x, Ya[k]);
            O.u2.y = fma2p(Q2, V.u2.y, Yb[k]);
            __stcs(op + 32 * k, O.f4);
        }
    }
}

extern "C" void kernel_launch(void* const* d_in, const int* in_sizes, int n_in,
                              void* d_out, int out_size)
{
    const float* x      = (const float*)d_in[0];
    const float* lt_in  = (const float*)d_in[1];
    const float* lt_out = (const float*)d_in[2];
    const float* la_in  = (const float*)d_in[3];
    const float* la_out = (const float*)d_in[4];
    const float* lkb    = (const float*)d_in[5];
    const float* lkd    = (const float*)d_in[6];
    const float* ema_x  = (const float*)d_in[7];
    const float* ema_x2 = (const float*)d_in[8];
    const float* ema_y  = (const float*)d_in[9];
    const float* ema_y2 = (const float*)d_in[10];
    const float* buf    = (const float*)d_in[11];
    const float* facil  = (const float*)d_in[12];

    const int M = in_sizes[0] / D_;   // 16384
    const int N = in_sizes[11] / D_;  // 512
    float* out = (float*)d_out;

    k_pass1<<<GRID1, BLK>>>(x, ema_x, ema_x2, ema_y, ema_y2,
                            lt_in, lt_out, la_in, la_out, M);
    k_mid<<<N, 128>>>(buf, facil, lkb, lkd, N, 1.0f / (float)M);
    k_pass2<<<GRID2, BLK>>>(x, buf, out, M);
}